// round 5
// baseline (speedup 1.0000x reference)
#include <cuda_runtime.h>
#include <math.h>

#define Bn 4
#define Tn 2048
#define Dn 1024
#define Hn 16
#define DHn 64
#define NROWS (Bn*Tn)          // 8192

// Scratch (device globals: allocation-free rule)
__device__ float g_Q[Bn*Hn*Tn*DHn];      // [B,H,T,dh]
__device__ float g_K[Bn*Hn*Tn*DHn];
__device__ float g_V[Bn*Hn*Tn*DHn];
__device__ float g_attn[Bn*Tn*Dn];       // merged-head attention output [B,T,D]

// ---------------------------------------------------------------------------
// QKV projection: C[m,n] = sum_k x[m,k]*W[n,k] + b[n], written as [B,H,T,dh]
// 128x128x8 tiles, 256 threads, 8x8 microtile, register prefetch.
// ---------------------------------------------------------------------------
__global__ __launch_bounds__(256) void qkv_gemm(
    const float* __restrict__ x,
    const float* __restrict__ Wq, const float* __restrict__ bq,
    const float* __restrict__ Wk, const float* __restrict__ bk,
    const float* __restrict__ Wv, const float* __restrict__ bv)
{
    const int which = blockIdx.z;
    const float* __restrict__ W    = (which == 0) ? Wq : ((which == 1) ? Wk : Wv);
    const float* __restrict__ bias = (which == 0) ? bq : ((which == 1) ? bk : bv);
    float* __restrict__ dst        = (which == 0) ? g_Q : ((which == 1) ? g_K : g_V);

    __shared__ float As[8][128];
    __shared__ float Bs[8][128];

    const int tid  = threadIdx.x;
    const int bm   = blockIdx.y * 128;
    const int bn   = blockIdx.x * 128;
    const int lrow = tid >> 1;            // 0..127
    const int lk4  = (tid & 1) * 4;       // 0 or 4
    const int ty   = tid >> 4;            // 0..15
    const int tx   = tid & 15;            // 0..15

    float acc[8][8];
#pragma unroll
    for (int i = 0; i < 8; i++)
#pragma unroll
        for (int j = 0; j < 8; j++) acc[i][j] = 0.f;

    // prefetch first tile
    float4 av  = *(const float4*)&x[(bm + lrow) * Dn + lk4];
    float4 bv4 = *(const float4*)&W[(bn + lrow) * Dn + lk4];

    for (int kt = 0; kt < Dn / 8; ++kt) {
        __syncthreads();
        As[lk4 + 0][lrow] = av.x;  As[lk4 + 1][lrow] = av.y;
        As[lk4 + 2][lrow] = av.z;  As[lk4 + 3][lrow] = av.w;
        Bs[lk4 + 0][lrow] = bv4.x; Bs[lk4 + 1][lrow] = bv4.y;
        Bs[lk4 + 2][lrow] = bv4.z; Bs[lk4 + 3][lrow] = bv4.w;
        __syncthreads();

        if (kt + 1 < Dn / 8) {
            av  = *(const float4*)&x[(bm + lrow) * Dn + (kt + 1) * 8 + lk4];
            bv4 = *(const float4*)&W[(bn + lrow) * Dn + (kt + 1) * 8 + lk4];
        }

#pragma unroll
        for (int k = 0; k < 8; k++) {
            float4 a0 = *(const float4*)&As[k][ty * 8];
            float4 a1 = *(const float4*)&As[k][ty * 8 + 4];
            float4 b0 = *(const float4*)&Bs[k][tx * 8];
            float4 b1 = *(const float4*)&Bs[k][tx * 8 + 4];
            float ar[8] = {a0.x, a0.y, a0.z, a0.w, a1.x, a1.y, a1.z, a1.w};
            float br[8] = {b0.x, b0.y, b0.z, b0.w, b1.x, b1.y, b1.z, b1.w};
#pragma unroll
            for (int i = 0; i < 8; i++)
#pragma unroll
                for (int j = 0; j < 8; j++) acc[i][j] += ar[i] * br[j];
        }
    }

    // epilogue: add bias, scatter to [B,H,T,dh]
    float bb[8];
#pragma unroll
    for (int j = 0; j < 8; j++) bb[j] = bias[bn + tx * 8 + j];

#pragma unroll
    for (int i = 0; i < 8; i++) {
        const int row = bm + ty * 8 + i;   // b*T + t
        const int b_  = row >> 11;
        const int t   = row & (Tn - 1);
#pragma unroll
        for (int j = 0; j < 8; j++) {
            const int col = bn + tx * 8 + j;
            const int hh  = col >> 6;
            const int dd  = col & 63;
            dst[(((size_t)(b_ * Hn + hh) * Tn + t) << 6) + dd] = acc[i][j] + bb[j];
        }
    }
}

// ---------------------------------------------------------------------------
// Flash attention (fp32): per block one (b,h,qtile64). 256 threads.
// Smem tiles padded to 65 floats/row to avoid stride-64 bank conflicts.
// ---------------------------------------------------------------------------
__global__ __launch_bounds__(256) void attn_kernel()
{
    extern __shared__ float smem[];
    float* Qs  = smem;                 // 64*65
    float* KVs = smem + 64 * 65;       // 64*65 (K, then reused for V)
    float* Ss  = smem + 2 * 64 * 65;   // 64*65
    float* m_s = smem + 3 * 64 * 65;   // 64
    float* l_s = m_s + 64;             // 64
    float* f_s = l_s + 64;             // 64

    const int qt = blockIdx.x;         // 0..31
    const int h  = blockIdx.y;
    const int b  = blockIdx.z;
    const int bh = b * Hn + h;

    const float* __restrict__ Qp = g_Q + (size_t)bh * Tn * DHn;
    const float* __restrict__ Kp = g_K + (size_t)bh * Tn * DHn;
    const float* __restrict__ Vp = g_V + (size_t)bh * Tn * DHn;

    const int tid = threadIdx.x;
    const int ty  = tid >> 4;          // 0..15 (q-row group)
    const int tx  = tid & 15;          // 0..15 (col group)
    const int qbase = qt * 64;

    // load Q tile, pre-scaled by 1/sqrt(dh)
    for (int i = tid; i < 4096; i += 256) {
        const int r = i >> 6, c = i & 63;
        Qs[r * 65 + c] = Qp[(size_t)(qbase + r) * DHn + c] * 0.125f;
    }
    if (tid < 64) { m_s[tid] = -1e30f; l_s[tid] = 0.f; }

    float o[4][4];
#pragma unroll
    for (int i = 0; i < 4; i++)
#pragma unroll
        for (int j = 0; j < 4; j++) o[i][j] = 0.f;

    __syncthreads();

    for (int kt = 0; kt <= qt; ++kt) {
        const int kbase = kt * 64;
        // load K tile
        for (int i = tid; i < 4096; i += 256) {
            const int r = i >> 6, c = i & 63;
            KVs[r * 65 + c] = Kp[(size_t)(kbase + r) * DHn + c];
        }
        __syncthreads();

        // S = Q @ K^T   (each thread 4x4)
        float s[4][4];
#pragma unroll
        for (int i = 0; i < 4; i++)
#pragma unroll
            for (int j = 0; j < 4; j++) s[i][j] = 0.f;

#pragma unroll 4
        for (int kk = 0; kk < 64; kk++) {
            float a0 = Qs[(ty * 4 + 0) * 65 + kk];
            float a1 = Qs[(ty * 4 + 1) * 65 + kk];
            float a2 = Qs[(ty * 4 + 2) * 65 + kk];
            float a3 = Qs[(ty * 4 + 3) * 65 + kk];
            float c0 = KVs[(tx * 4 + 0) * 65 + kk];
            float c1 = KVs[(tx * 4 + 1) * 65 + kk];
            float c2 = KVs[(tx * 4 + 2) * 65 + kk];
            float c3 = KVs[(tx * 4 + 3) * 65 + kk];
            s[0][0] += a0 * c0; s[0][1] += a0 * c1; s[0][2] += a0 * c2; s[0][3] += a0 * c3;
            s[1][0] += a1 * c0; s[1][1] += a1 * c1; s[1][2] += a1 * c2; s[1][3] += a1 * c3;
            s[2][0] += a2 * c0; s[2][1] += a2 * c1; s[2][2] += a2 * c2; s[2][3] += a2 * c3;
            s[3][0] += a3 * c0; s[3][1] += a3 * c1; s[3][2] += a3 * c2; s[3][3] += a3 * c3;
        }

        // causal mask (only the diagonal tile needs it)
        if (kt == qt) {
#pragma unroll
            for (int i = 0; i < 4; i++)
#pragma unroll
                for (int j = 0; j < 4; j++)
                    if (kbase + tx * 4 + j > qbase + ty * 4 + i) s[i][j] = -1e30f;
        }
#pragma unroll
        for (int i = 0; i < 4; i++)
#pragma unroll
            for (int j = 0; j < 4; j++)
                Ss[(ty * 4 + i) * 65 + tx * 4 + j] = s[i][j];
        __syncthreads();

        // threads <64: online softmax for row tid; threads >=64: load V tile
        if (tid < 64) {
            const int r = tid;
            float mt = -1e30f;
            for (int c = 0; c < 64; c++) mt = fmaxf(mt, Ss[r * 65 + c]);
            const float mold = m_s[r];
            const float mnew = fmaxf(mold, mt);
            const float f = __expf(mold - mnew);
            float sum = 0.f;
            for (int c = 0; c < 64; c++) {
                const float p = __expf(Ss[r * 65 + c] - mnew);
                Ss[r * 65 + c] = p;
                sum += p;
            }
            l_s[r] = l_s[r] * f + sum;
            m_s[r] = mnew;
            f_s[r] = f;
        } else {
            for (int i = tid - 64; i < 4096; i += 192) {
                const int r = i >> 6, c = i & 63;
                KVs[r * 65 + c] = Vp[(size_t)(kbase + r) * DHn + c];
            }
        }
        __syncthreads();

        // O = O*f + P @ V
#pragma unroll
        for (int i = 0; i < 4; i++) {
            const float f = f_s[ty * 4 + i];
#pragma unroll
            for (int j = 0; j < 4; j++) o[i][j] *= f;
        }
#pragma unroll 4
        for (int c = 0; c < 64; c++) {
            float p0 = Ss[(ty * 4 + 0) * 65 + c];
            float p1 = Ss[(ty * 4 + 1) * 65 + c];
            float p2 = Ss[(ty * 4 + 2) * 65 + c];
            float p3 = Ss[(ty * 4 + 3) * 65 + c];
            float v0 = KVs[c * 65 + tx * 4 + 0];
            float v1 = KVs[c * 65 + tx * 4 + 1];
            float v2 = KVs[c * 65 + tx * 4 + 2];
            float v3 = KVs[c * 65 + tx * 4 + 3];
            o[0][0] += p0 * v0; o[0][1] += p0 * v1; o[0][2] += p0 * v2; o[0][3] += p0 * v3;
            o[1][0] += p1 * v0; o[1][1] += p1 * v1; o[1][2] += p1 * v2; o[1][3] += p1 * v3;
            o[2][0] += p2 * v0; o[2][1] += p2 * v1; o[2][2] += p2 * v2; o[2][3] += p2 * v3;
            o[3][0] += p3 * v0; o[3][1] += p3 * v1; o[3][2] += p3 * v2; o[3][3] += p3 * v3;
        }
        __syncthreads();
    }

    // write out merged heads: g_attn[b, t, h*64+dd]
#pragma unroll
    for (int i = 0; i < 4; i++) {
        const int row = qbase + ty * 4 + i;
        const float inv = 1.f / l_s[ty * 4 + i];
#pragma unroll
        for (int j = 0; j < 4; j++) {
            g_attn[((size_t)(b * Tn + row)) * Dn + h * 64 + tx * 4 + j] = o[i][j] * inv;
        }
    }
}

// ---------------------------------------------------------------------------
// Residual + LayerNorm: one block per row of 1024.
// ---------------------------------------------------------------------------
__global__ __launch_bounds__(256) void resid_ln(
    const float* __restrict__ x,
    const float* __restrict__ gamma,
    const float* __restrict__ beta,
    float* __restrict__ out)
{
    const int row = blockIdx.x;
    const int tid = threadIdx.x;
    const float* xr = x + (size_t)row * Dn;
    const float* ar = g_attn + (size_t)row * Dn;

    float v[4];
    float s = 0.f, sq = 0.f;
#pragma unroll
    for (int j = 0; j < 4; j++) {
        const int c = tid + j * 256;
        const float val = ar[c] + xr[c];
        v[j] = val;
        s += val;
        sq += val * val;
    }

    // warp reduce
#pragma unroll
    for (int off = 16; off > 0; off >>= 1) {
        s  += __shfl_down_sync(0xffffffffu, s, off);
        sq += __shfl_down_sync(0xffffffffu, sq, off);
    }
    __shared__ float sh[16];
    const int wid = tid >> 5, lane = tid & 31;
    if (lane == 0) { sh[wid] = s; sh[wid + 8] = sq; }
    __syncthreads();
    if (wid == 0) {
        float a  = (lane < 8) ? sh[lane] : 0.f;
        float b2 = (lane < 8) ? sh[lane + 8] : 0.f;
#pragma unroll
        for (int off = 4; off > 0; off >>= 1) {
            a  += __shfl_down_sync(0xffffffffu, a, off);
            b2 += __shfl_down_sync(0xffffffffu, b2, off);
        }
        if (lane == 0) {
            const float mean = a * (1.f / Dn);
            const float var  = b2 * (1.f / Dn) - mean * mean;
            sh[0] = mean;
            sh[1] = rsqrtf(var + 1e-5f);
        }
    }
    __syncthreads();
    const float mean = sh[0], rstd = sh[1];
#pragma unroll
    for (int j = 0; j < 4; j++) {
        const int c = tid + j * 256;
        out[(size_t)row * Dn + c] = (v[j] - mean) * rstd * gamma[c] + beta[c];
    }
}

// ---------------------------------------------------------------------------
extern "C" void kernel_launch(void* const* d_in, const int* in_sizes, int n_in,
                              void* d_out, int out_size)
{
    const float* x     = (const float*)d_in[0];
    const float* Wq    = (const float*)d_in[1];
    const float* bq    = (const float*)d_in[2];
    const float* Wk    = (const float*)d_in[3];
    const float* bk    = (const float*)d_in[4];
    const float* Wv    = (const float*)d_in[5];
    const float* bv    = (const float*)d_in[6];
    const float* gamma = (const float*)d_in[7];
    const float* beta  = (const float*)d_in[8];
    // d_in[9] = n_heads (compile-time 16)
    float* out = (float*)d_out;

    // QKV projections: grid (N/128, M/128, 3)
    qkv_gemm<<<dim3(Dn / 128, NROWS / 128, 3), 256>>>(x, Wq, bq, Wk, bk, Wv, bv);

    // Flash attention
    const int attn_smem = (3 * 64 * 65 + 3 * 64) * (int)sizeof(float);  // 50688 B
    static bool attr_set = false;
    if (!attr_set) {
        cudaFuncSetAttribute(attn_kernel, cudaFuncAttributeMaxDynamicSharedMemorySize, attn_smem);
        attr_set = true;
    }
    attn_kernel<<<dim3(Tn / 64, Hn, Bn), 256, attn_smem>>>();

    // Residual + LayerNorm
    resid_ln<<<NROWS, 256>>>(x, gamma, beta, out);
}

// round 9
// speedup vs baseline: 1.4009x; 1.4009x over previous
#include <cuda_runtime.h>
#include <cuda_bf16.h>
#include <math.h>
#include <stdint.h>

#define Bn 4
#define Tn 2048
#define Dn 1024
#define Hn 16
#define DHn 64
#define NROWS (Bn*Tn)          // 8192

// ---------------------------------------------------------------------------
// Device scratch (allocation-free rule: __device__ globals)
// ---------------------------------------------------------------------------
__device__ float g_Q[Bn*Hn*Tn*DHn];      // [B,H,T,dh]
__device__ float g_K[Bn*Hn*Tn*DHn];
__device__ float g_V[Bn*Hn*Tn*DHn];
__device__ float g_attn[Bn*Tn*Dn];       // merged-head attn out [B,T,D]

__device__ __nv_bfloat16 g_xhi[NROWS*Dn];
__device__ __nv_bfloat16 g_xlo[NROWS*Dn];
__device__ __nv_bfloat16 g_Whi[3][Dn*Dn];
__device__ __nv_bfloat16 g_Wlo[3][Dn*Dn];

// ---------------------------------------------------------------------------
// Generic-PTX helpers (NO tcgen05 — harness compiles plain compute_103 PTX,
// which rejects all sm_103a-only instructions).
// ---------------------------------------------------------------------------
__device__ __forceinline__ uint32_t smem_u32(const void* p) {
    uint32_t a;
    asm("{ .reg .u64 t; cvta.to.shared.u64 t, %1; cvt.u32.u64 %0, t; }" : "=r"(a) : "l"(p));
    return a;
}
__device__ __forceinline__ uint32_t sw128(uint32_t off) { return off ^ ((off >> 3) & 0x70); }

__device__ __forceinline__ void cp_async16(uint32_t saddr, const void* gaddr) {
    asm volatile("cp.async.cg.shared.global [%0], [%1], 16;\n" :: "r"(saddr), "l"(gaddr));
}
#define CP_COMMIT() asm volatile("cp.async.commit_group;\n" ::: "memory")
#define CP_WAIT(N)  asm volatile("cp.async.wait_group %0;\n" :: "n"(N) : "memory")

__device__ __forceinline__ void ldm_x4(uint32_t* r, uint32_t addr) {
    asm volatile("ldmatrix.sync.aligned.m8n8.x4.shared.b16 {%0,%1,%2,%3}, [%4];"
        : "=r"(r[0]), "=r"(r[1]), "=r"(r[2]), "=r"(r[3]) : "r"(addr));
}
__device__ __forceinline__ void mma_bf16(float* c, const uint32_t* a, const uint32_t* b) {
    asm volatile(
        "mma.sync.aligned.m16n8k16.row.col.f32.bf16.bf16.f32 "
        "{%0,%1,%2,%3}, {%4,%5,%6,%7}, {%8,%9}, {%0,%1,%2,%3};"
        : "+f"(c[0]), "+f"(c[1]), "+f"(c[2]), "+f"(c[3])
        : "r"(a[0]), "r"(a[1]), "r"(a[2]), "r"(a[3]), "r"(b[0]), "r"(b[1]));
}

// ---------------------------------------------------------------------------
// fp32 -> bf16 hi/lo split
// ---------------------------------------------------------------------------
__global__ __launch_bounds__(256) void split_bf16(
    const float* __restrict__ src, __nv_bfloat16* __restrict__ hi,
    __nv_bfloat16* __restrict__ lo, int n4)
{
    const int i = blockIdx.x * 256 + threadIdx.x;
    if (i >= n4) return;
    float4 v = ((const float4*)src)[i];
    __nv_bfloat16 h0 = __float2bfloat16(v.x), h1 = __float2bfloat16(v.y);
    __nv_bfloat16 h2 = __float2bfloat16(v.z), h3 = __float2bfloat16(v.w);
    __nv_bfloat16 l0 = __float2bfloat16(v.x - __bfloat162float(h0));
    __nv_bfloat16 l1 = __float2bfloat16(v.y - __bfloat162float(h1));
    __nv_bfloat16 l2 = __float2bfloat16(v.z - __bfloat162float(h2));
    __nv_bfloat16 l3 = __float2bfloat16(v.w - __bfloat162float(h3));
    ushort4 hv, lv;
    hv.x = *(unsigned short*)&h0; hv.y = *(unsigned short*)&h1;
    hv.z = *(unsigned short*)&h2; hv.w = *(unsigned short*)&h3;
    lv.x = *(unsigned short*)&l0; lv.y = *(unsigned short*)&l1;
    lv.z = *(unsigned short*)&l2; lv.w = *(unsigned short*)&l3;
    ((ushort4*)hi)[i] = hv;
    ((ushort4*)lo)[i] = lv;
}

// ---------------------------------------------------------------------------
// mma.sync bf16 QKV projection: C = x @ W^T + b (3-pass split-bf16 fp32 emu).
// CTA 128x128; K chunks of 64 bf16; SW128 smem; cp.async double buffer.
// 8 warps: warp_m = wid&3 (32 rows), warp_n = wid>>2 (64 cols).
// ---------------------------------------------------------------------------
#define GK_BUF   32768                  // A(16K)+B(16K) per buffer
#define GK_SMEM  (2*GK_BUF)             // 64 KB

__global__ __launch_bounds__(256, 1) void qkv_gemm_mma(
    const float* __restrict__ bq, const float* __restrict__ bk,
    const float* __restrict__ bv)
{
    extern __shared__ char sm[];

    const int tid  = threadIdx.x;
    const int lane = tid & 31;
    const int wid  = tid >> 5;
    const int warp_m = wid & 3;         // 0..3  (32 rows each)
    const int warp_n = wid >> 2;        // 0..1  (64 cols each)
    const int which = blockIdx.z;
    const int bn = blockIdx.x * 128;
    const int bm = blockIdx.y * 128;

    const __nv_bfloat16* __restrict__ Whi = g_Whi[which];
    const __nv_bfloat16* __restrict__ Wlo = g_Wlo[which];
    const float* __restrict__ bias = (which == 0) ? bq : ((which == 1) ? bk : bv);
    float* __restrict__ dst = (which == 0) ? g_Q : ((which == 1) ? g_K : g_V);

    float acc[2][8][4];
#pragma unroll
    for (int mt = 0; mt < 2; mt++)
#pragma unroll
        for (int nt = 0; nt < 8; nt++)
#pragma unroll
            for (int j = 0; j < 4; j++) acc[mt][nt][j] = 0.f;

    // per-thread load slots: 4 A-chunks + 4 B-chunks of 16B per tile
    const int row_ld = tid >> 1;                    // used below via v
    (void)row_ld;

    // ---- issue tile ci into buffer buf ----
    auto issue_tile = [&](int ci, int buf) {
        const int pass = ci >> 4;                   // 0 hi*hi, 1 hi*lo, 2 lo*hi
        const int kc   = (ci & 15) * 64;
        const __nv_bfloat16* __restrict__ Asrc = (pass == 2) ? g_xlo : g_xhi;
        const __nv_bfloat16* __restrict__ Bsrc = (pass == 1) ? Wlo : Whi;
        char* ab = sm + buf * GK_BUF;
#pragma unroll
        for (int it = 0; it < 4; ++it) {
            const int v = tid + it * 256;           // 0..1023
            const int row = v >> 3, c16 = v & 7;
            const uint32_t soff = sw128(row * 128 + c16 * 16);
            cp_async16(smem_u32(ab + soff),
                       &Asrc[(size_t)(bm + row) * Dn + kc + c16 * 8]);
            cp_async16(smem_u32(ab + 16384 + soff),
                       &Bsrc[(size_t)(bn + row) * Dn + kc + c16 * 8]);
        }
        CP_COMMIT();
    };

    issue_tile(0, 0);

    for (int ci = 0; ci < 48; ++ci) {
        const int buf = ci & 1;
        if (ci + 1 < 48) {
            issue_tile(ci + 1, (ci + 1) & 1);
            CP_WAIT(1);
        } else {
            CP_WAIT(0);
        }
        __syncthreads();

        const uint32_t Abase = smem_u32(sm + buf * GK_BUF);
        const uint32_t Bbase = Abase + 16384;

#pragma unroll
        for (int kk8 = 0; kk8 < 8; kk8 += 2) {      // k16 step: elements kk8*8
            uint32_t a[2][4], b[4][4];
            // A fragments: m16k16 each, ldmatrix x4 non-trans
#pragma unroll
            for (int mt = 0; mt < 2; ++mt) {
                const int row = warp_m * 32 + mt * 16 + (lane & 15);
                const uint32_t addr =
                    Abase + sw128(row * 128 + (kk8 + (lane >> 4)) * 16);
                ldm_x4(a[mt], addr);
            }
            // B fragments: n16k16 per x4 (W rows are K-contig = col-major B)
#pragma unroll
            for (int ng = 0; ng < 4; ++ng) {
                const int mat  = lane >> 3;         // 0..3
                const int nrow = warp_n * 64 + ng * 16 + ((mat >> 1) << 3) + (lane & 7);
                const uint32_t addr =
                    Bbase + sw128(nrow * 128 + (kk8 + (mat & 1)) * 16);
                ldm_x4(b[ng], addr);
            }
#pragma unroll
            for (int mt = 0; mt < 2; ++mt)
#pragma unroll
                for (int nt = 0; nt < 8; ++nt)
                    mma_bf16(acc[mt][nt], a[mt], &b[nt >> 1][(nt & 1) * 2]);
        }
        __syncthreads();
    }

    // ---- epilogue: bias add + scatter to [B,H,T,dh] ----
#pragma unroll
    for (int mt = 0; mt < 2; ++mt) {
        const int r0 = bm + warp_m * 32 + mt * 16 + (lane >> 2);
        const int r1 = r0 + 8;
        const int b0_ = r0 >> 11, t0 = r0 & (Tn - 1);
        const int b1_ = r1 >> 11, t1 = r1 & (Tn - 1);
#pragma unroll
        for (int nt = 0; nt < 8; ++nt) {
            const int col = bn + warp_n * 64 + nt * 8 + (lane & 3) * 2;
            const int hh = col >> 6, dd = col & 63;
            const float bb0 = bias[col], bb1 = bias[col + 1];
            float2 w0 = make_float2(acc[mt][nt][0] + bb0, acc[mt][nt][1] + bb1);
            float2 w1 = make_float2(acc[mt][nt][2] + bb0, acc[mt][nt][3] + bb1);
            *(float2*)&dst[(((size_t)(b0_ * Hn + hh) * Tn + t0) << 6) + dd] = w0;
            *(float2*)&dst[(((size_t)(b1_ * Hn + hh) * Tn + t1) << 6) + dd] = w1;
        }
    }
}

// ---------------------------------------------------------------------------
// Flash attention (fp32), unchanged.
// ---------------------------------------------------------------------------
__global__ __launch_bounds__(256) void attn_kernel()
{
    extern __shared__ float smem[];
    float* Qs  = smem;
    float* KVs = smem + 64 * 65;
    float* Ss  = smem + 2 * 64 * 65;
    float* m_s = smem + 3 * 64 * 65;
    float* l_s = m_s + 64;
    float* f_s = l_s + 64;

    const int qt = blockIdx.x;
    const int h  = blockIdx.y;
    const int b  = blockIdx.z;
    const int bh = b * Hn + h;

    const float* __restrict__ Qp = g_Q + (size_t)bh * Tn * DHn;
    const float* __restrict__ Kp = g_K + (size_t)bh * Tn * DHn;
    const float* __restrict__ Vp = g_V + (size_t)bh * Tn * DHn;

    const int tid = threadIdx.x;
    const int ty  = tid >> 4;
    const int tx  = tid & 15;
    const int qbase = qt * 64;

    for (int i = tid; i < 4096; i += 256) {
        const int r = i >> 6, c = i & 63;
        Qs[r * 65 + c] = Qp[(size_t)(qbase + r) * DHn + c] * 0.125f;
    }
    if (tid < 64) { m_s[tid] = -1e30f; l_s[tid] = 0.f; }

    float o[4][4];
#pragma unroll
    for (int i = 0; i < 4; i++)
#pragma unroll
        for (int j = 0; j < 4; j++) o[i][j] = 0.f;

    __syncthreads();

    for (int kt = 0; kt <= qt; ++kt) {
        const int kbase = kt * 64;
        for (int i = tid; i < 4096; i += 256) {
            const int r = i >> 6, c = i & 63;
            KVs[r * 65 + c] = Kp[(size_t)(kbase + r) * DHn + c];
        }
        __syncthreads();

        float s[4][4];
#pragma unroll
        for (int i = 0; i < 4; i++)
#pragma unroll
            for (int j = 0; j < 4; j++) s[i][j] = 0.f;

#pragma unroll 4
        for (int kk = 0; kk < 64; kk++) {
            float a0 = Qs[(ty * 4 + 0) * 65 + kk];
            float a1 = Qs[(ty * 4 + 1) * 65 + kk];
            float a2 = Qs[(ty * 4 + 2) * 65 + kk];
            float a3 = Qs[(ty * 4 + 3) * 65 + kk];
            float c0 = KVs[(tx * 4 + 0) * 65 + kk];
            float c1 = KVs[(tx * 4 + 1) * 65 + kk];
            float c2 = KVs[(tx * 4 + 2) * 65 + kk];
            float c3 = KVs[(tx * 4 + 3) * 65 + kk];
            s[0][0] += a0 * c0; s[0][1] += a0 * c1; s[0][2] += a0 * c2; s[0][3] += a0 * c3;
            s[1][0] += a1 * c0; s[1][1] += a1 * c1; s[1][2] += a1 * c2; s[1][3] += a1 * c3;
            s[2][0] += a2 * c0; s[2][1] += a2 * c1; s[2][2] += a2 * c2; s[2][3] += a2 * c3;
            s[3][0] += a3 * c0; s[3][1] += a3 * c1; s[3][2] += a3 * c2; s[3][3] += a3 * c3;
        }

        if (kt == qt) {
#pragma unroll
            for (int i = 0; i < 4; i++)
#pragma unroll
                for (int j = 0; j < 4; j++)
                    if (kbase + tx * 4 + j > qbase + ty * 4 + i) s[i][j] = -1e30f;
        }
#pragma unroll
        for (int i = 0; i < 4; i++)
#pragma unroll
            for (int j = 0; j < 4; j++)
                Ss[(ty * 4 + i) * 65 + tx * 4 + j] = s[i][j];
        __syncthreads();

        if (tid < 64) {
            const int r = tid;
            float mt = -1e30f;
            for (int c = 0; c < 64; c++) mt = fmaxf(mt, Ss[r * 65 + c]);
            const float mold = m_s[r];
            const float mnew = fmaxf(mold, mt);
            const float f = __expf(mold - mnew);
            float sum = 0.f;
            for (int c = 0; c < 64; c++) {
                const float p = __expf(Ss[r * 65 + c] - mnew);
                Ss[r * 65 + c] = p;
                sum += p;
            }
            l_s[r] = l_s[r] * f + sum;
            m_s[r] = mnew;
            f_s[r] = f;
        } else {
            for (int i = tid - 64; i < 4096; i += 192) {
                const int r = i >> 6, c = i & 63;
                KVs[r * 65 + c] = Vp[(size_t)(kbase + r) * DHn + c];
            }
        }
        __syncthreads();

#pragma unroll
        for (int i = 0; i < 4; i++) {
            const float f = f_s[ty * 4 + i];
#pragma unroll
            for (int j = 0; j < 4; j++) o[i][j] *= f;
        }
#pragma unroll 4
        for (int c = 0; c < 64; c++) {
            float p0 = Ss[(ty * 4 + 0) * 65 + c];
            float p1 = Ss[(ty * 4 + 1) * 65 + c];
            float p2 = Ss[(ty * 4 + 2) * 65 + c];
            float p3 = Ss[(ty * 4 + 3) * 65 + c];
            float v0 = KVs[c * 65 + tx * 4 + 0];
            float v1 = KVs[c * 65 + tx * 4 + 1];
            float v2 = KVs[c * 65 + tx * 4 + 2];
            float v3 = KVs[c * 65 + tx * 4 + 3];
            o[0][0] += p0 * v0; o[0][1] += p0 * v1; o[0][2] += p0 * v2; o[0][3] += p0 * v3;
            o[1][0] += p1 * v0; o[1][1] += p1 * v1; o[1][2] += p1 * v2; o[1][3] += p1 * v3;
            o[2][0] += p2 * v0; o[2][1] += p2 * v1; o[2][2] += p2 * v2; o[2][3] += p2 * v3;
            o[3][0] += p3 * v0; o[3][1] += p3 * v1; o[3][2] += p3 * v2; o[3][3] += p3 * v3;
        }
        __syncthreads();
    }

#pragma unroll
    for (int i = 0; i < 4; i++) {
        const int row = qbase + ty * 4 + i;
        const float inv = 1.f / l_s[ty * 4 + i];
#pragma unroll
        for (int j = 0; j < 4; j++) {
            g_attn[((size_t)(b * Tn + row)) * Dn + h * 64 + tx * 4 + j] = o[i][j] * inv;
        }
    }
}

// ---------------------------------------------------------------------------
// Residual + LayerNorm
// ---------------------------------------------------------------------------
__global__ __launch_bounds__(256) void resid_ln(
    const float* __restrict__ x,
    const float* __restrict__ gamma,
    const float* __restrict__ beta,
    float* __restrict__ out)
{
    const int row = blockIdx.x;
    const int tid = threadIdx.x;
    const float* xr = x + (size_t)row * Dn;
    const float* ar = g_attn + (size_t)row * Dn;

    float v[4];
    float s = 0.f, sq = 0.f;
#pragma unroll
    for (int j = 0; j < 4; j++) {
        const int c = tid + j * 256;
        const float val = ar[c] + xr[c];
        v[j] = val;
        s += val;
        sq += val * val;
    }
#pragma unroll
    for (int off = 16; off > 0; off >>= 1) {
        s  += __shfl_down_sync(0xffffffffu, s, off);
        sq += __shfl_down_sync(0xffffffffu, sq, off);
    }
    __shared__ float sh[16];
    const int wid = tid >> 5, lane = tid & 31;
    if (lane == 0) { sh[wid] = s; sh[wid + 8] = sq; }
    __syncthreads();
    if (wid == 0) {
        float a  = (lane < 8) ? sh[lane] : 0.f;
        float b2 = (lane < 8) ? sh[lane + 8] : 0.f;
#pragma unroll
        for (int off = 4; off > 0; off >>= 1) {
            a  += __shfl_down_sync(0xffffffffu, a, off);
            b2 += __shfl_down_sync(0xffffffffu, b2, off);
        }
        if (lane == 0) {
            const float mean = a * (1.f / Dn);
            const float var  = b2 * (1.f / Dn) - mean * mean;
            sh[0] = mean;
            sh[1] = rsqrtf(var + 1e-5f);
        }
    }
    __syncthreads();
    const float mean = sh[0], rstd = sh[1];
#pragma unroll
    for (int j = 0; j < 4; j++) {
        const int c = tid + j * 256;
        out[(size_t)row * Dn + c] = (v[j] - mean) * rstd * gamma[c] + beta[c];
    }
}

// ---------------------------------------------------------------------------
extern "C" void kernel_launch(void* const* d_in, const int* in_sizes, int n_in,
                              void* d_out, int out_size)
{
    const float* x     = (const float*)d_in[0];
    const float* Wq    = (const float*)d_in[1];
    const float* bq    = (const float*)d_in[2];
    const float* Wk    = (const float*)d_in[3];
    const float* bk    = (const float*)d_in[4];
    const float* Wv    = (const float*)d_in[5];
    const float* bv    = (const float*)d_in[6];
    const float* gamma = (const float*)d_in[7];
    const float* beta  = (const float*)d_in[8];
    float* out = (float*)d_out;

    const int attn_smem = (3 * 64 * 65 + 3 * 64) * (int)sizeof(float);
    static bool attr_set = false;
    if (!attr_set) {
        cudaFuncSetAttribute(attn_kernel, cudaFuncAttributeMaxDynamicSharedMemorySize, attn_smem);
        cudaFuncSetAttribute(qkv_gemm_mma, cudaFuncAttributeMaxDynamicSharedMemorySize, GK_SMEM);
        attr_set = true;
    }

    // bf16 hi/lo splits
    __nv_bfloat16 *xhi, *xlo, *whi, *wlo;
    cudaGetSymbolAddress((void**)&xhi, g_xhi);
    cudaGetSymbolAddress((void**)&xlo, g_xlo);
    cudaGetSymbolAddress((void**)&whi, g_Whi);
    cudaGetSymbolAddress((void**)&wlo, g_Wlo);

    split_bf16<<<(NROWS * Dn / 4 + 255) / 256, 256>>>(x, xhi, xlo, NROWS * Dn / 4);
    split_bf16<<<(Dn * Dn / 4 + 255) / 256, 256>>>(Wq, whi + 0 * (size_t)Dn * Dn, wlo + 0 * (size_t)Dn * Dn, Dn * Dn / 4);
    split_bf16<<<(Dn * Dn / 4 + 255) / 256, 256>>>(Wk, whi + 1 * (size_t)Dn * Dn, wlo + 1 * (size_t)Dn * Dn, Dn * Dn / 4);
    split_bf16<<<(Dn * Dn / 4 + 255) / 256, 256>>>(Wv, whi + 2 * (size_t)Dn * Dn, wlo + 2 * (size_t)Dn * Dn, Dn * Dn / 4);

    // tensor-core QKV projections (mma.sync bf16, 3-pass split)
    qkv_gemm_mma<<<dim3(Dn / 128, NROWS / 128, 3), 256, GK_SMEM>>>(bq, bk, bv);

    // Flash attention (fp32)
    attn_kernel<<<dim3(Tn / 64, Hn, Bn), 256, attn_smem>>>();

    // Residual + LayerNorm
    resid_ln<<<NROWS, 256>>>(x, gamma, beta, out);
}

// round 12
// speedup vs baseline: 3.0370x; 2.1678x over previous
#include <cuda_runtime.h>
#include <cuda_bf16.h>
#include <math.h>
#include <stdint.h>

#define Bn 4
#define Tn 2048
#define Dn 1024
#define Hn 16
#define DHn 64
#define NROWS (Bn*Tn)          // 8192

// ---------------------------------------------------------------------------
// Device scratch (allocation-free rule: __device__ globals)
// ---------------------------------------------------------------------------
__device__ float g_attn[Bn*Tn*Dn];       // merged-head attn out [B,T,D]

__device__ __nv_bfloat16 g_xhi[NROWS*Dn];
__device__ __nv_bfloat16 g_xlo[NROWS*Dn];
__device__ __nv_bfloat16 g_Whi[3][Dn*Dn];
__device__ __nv_bfloat16 g_Wlo[3][Dn*Dn];

// Q/K/V in bf16 hi/lo, layout [B,H,T,dh]
__device__ __nv_bfloat16 g_qhi[Bn*Hn*Tn*DHn];
__device__ __nv_bfloat16 g_qlo[Bn*Hn*Tn*DHn];
__device__ __nv_bfloat16 g_khi[Bn*Hn*Tn*DHn];
__device__ __nv_bfloat16 g_klo[Bn*Hn*Tn*DHn];
__device__ __nv_bfloat16 g_vhi[Bn*Hn*Tn*DHn];
__device__ __nv_bfloat16 g_vlo[Bn*Hn*Tn*DHn];

// ---------------------------------------------------------------------------
// Generic-PTX helpers (NO tcgen05 — harness targets plain compute_103)
// ---------------------------------------------------------------------------
__device__ __forceinline__ uint32_t smem_u32(const void* p) {
    uint32_t a;
    asm("{ .reg .u64 t; cvta.to.shared.u64 t, %1; cvt.u32.u64 %0, t; }" : "=r"(a) : "l"(p));
    return a;
}
__device__ __forceinline__ uint32_t sw128(uint32_t off) { return off ^ ((off >> 3) & 0x70); }

__device__ __forceinline__ void cp_async16(uint32_t saddr, const void* gaddr) {
    asm volatile("cp.async.cg.shared.global [%0], [%1], 16;\n" :: "r"(saddr), "l"(gaddr));
}
#define CP_COMMIT() asm volatile("cp.async.commit_group;\n" ::: "memory")
#define CP_WAIT(N)  asm volatile("cp.async.wait_group %0;\n" :: "n"(N) : "memory")

__device__ __forceinline__ void ldm_x4(uint32_t* r, uint32_t addr) {
    asm volatile("ldmatrix.sync.aligned.m8n8.x4.shared.b16 {%0,%1,%2,%3}, [%4];"
        : "=r"(r[0]), "=r"(r[1]), "=r"(r[2]), "=r"(r[3]) : "r"(addr));
}
__device__ __forceinline__ void ldm_x4t(uint32_t* r, uint32_t addr) {
    asm volatile("ldmatrix.sync.aligned.m8n8.x4.trans.shared.b16 {%0,%1,%2,%3}, [%4];"
        : "=r"(r[0]), "=r"(r[1]), "=r"(r[2]), "=r"(r[3]) : "r"(addr));
}
__device__ __forceinline__ void mma_bf16(float* c, const uint32_t* a, const uint32_t* b) {
    asm volatile(
        "mma.sync.aligned.m16n8k16.row.col.f32.bf16.bf16.f32 "
        "{%0,%1,%2,%3}, {%4,%5,%6,%7}, {%8,%9}, {%0,%1,%2,%3};"
        : "+f"(c[0]), "+f"(c[1]), "+f"(c[2]), "+f"(c[3])
        : "r"(a[0]), "r"(a[1]), "r"(a[2]), "r"(a[3]), "r"(b[0]), "r"(b[1]));
}

// split a float pair into packed bf16 hi + bf16 lo(residual)
__device__ __forceinline__ void split2(float a, float b, uint32_t& hi, uint32_t& lo) {
    __nv_bfloat162 h = __floats2bfloat162_rn(a, b);
    float ra = a - __low2float(h);
    float rb = b - __high2float(h);
    __nv_bfloat162 l = __floats2bfloat162_rn(ra, rb);
    hi = *(uint32_t*)&h;
    lo = *(uint32_t*)&l;
}

// ---------------------------------------------------------------------------
// fp32 -> bf16 hi/lo split (for x and W)
// ---------------------------------------------------------------------------
__global__ __launch_bounds__(256) void split_bf16(
    const float* __restrict__ src, __nv_bfloat16* __restrict__ hi,
    __nv_bfloat16* __restrict__ lo, int n4)
{
    const int i = blockIdx.x * 256 + threadIdx.x;
    if (i >= n4) return;
    float4 v = ((const float4*)src)[i];
    uint32_t h0, l0, h1, l1;
    split2(v.x, v.y, h0, l0);
    split2(v.z, v.w, h1, l1);
    uint2 hv = make_uint2(h0, h1), lv = make_uint2(l0, l1);
    ((uint2*)hi)[i] = hv;
    ((uint2*)lo)[i] = lv;
}

// ---------------------------------------------------------------------------
// mma.sync bf16 QKV projection: C = x @ W^T + b (3-pass split-bf16 fp32 emu).
// Epilogue writes bf16 hi/lo pairs to [B,H,T,dh] arrays (Q scaled by 0.125).
// ---------------------------------------------------------------------------
#define GK_BUF   32768
#define GK_SMEM  (2*GK_BUF)

__global__ __launch_bounds__(256, 1) void qkv_gemm_mma(
    const float* __restrict__ bq, const float* __restrict__ bk,
    const float* __restrict__ bv)
{
    extern __shared__ char sm[];

    const int tid  = threadIdx.x;
    const int lane = tid & 31;
    const int wid  = tid >> 5;
    const int warp_m = wid & 3;
    const int warp_n = wid >> 2;
    const int which = blockIdx.z;
    const int bn = blockIdx.x * 128;
    const int bm = blockIdx.y * 128;

    const __nv_bfloat16* __restrict__ Whi = g_Whi[which];
    const __nv_bfloat16* __restrict__ Wlo = g_Wlo[which];
    const float* __restrict__ bias = (which == 0) ? bq : ((which == 1) ? bk : bv);
    __nv_bfloat16* __restrict__ dhi = (which == 0) ? g_qhi : ((which == 1) ? g_khi : g_vhi);
    __nv_bfloat16* __restrict__ dlo = (which == 0) ? g_qlo : ((which == 1) ? g_klo : g_vlo);
    const float sc = (which == 0) ? 0.125f : 1.0f;

    float acc[2][8][4];
#pragma unroll
    for (int mt = 0; mt < 2; mt++)
#pragma unroll
        for (int nt = 0; nt < 8; nt++)
#pragma unroll
            for (int j = 0; j < 4; j++) acc[mt][nt][j] = 0.f;

    auto issue_tile = [&](int ci, int buf) {
        const int pass = ci >> 4;
        const int kc   = (ci & 15) * 64;
        const __nv_bfloat16* __restrict__ Asrc = (pass == 2) ? g_xlo : g_xhi;
        const __nv_bfloat16* __restrict__ Bsrc = (pass == 1) ? Wlo : Whi;
        char* ab = sm + buf * GK_BUF;
#pragma unroll
        for (int it = 0; it < 4; ++it) {
            const int v = tid + it * 256;
            const int row = v >> 3, c16 = v & 7;
            const uint32_t soff = sw128(row * 128 + c16 * 16);
            cp_async16(smem_u32(ab + soff),
                       &Asrc[(size_t)(bm + row) * Dn + kc + c16 * 8]);
            cp_async16(smem_u32(ab + 16384 + soff),
                       &Bsrc[(size_t)(bn + row) * Dn + kc + c16 * 8]);
        }
        CP_COMMIT();
    };

    issue_tile(0, 0);

    for (int ci = 0; ci < 48; ++ci) {
        const int buf = ci & 1;
        if (ci + 1 < 48) {
            issue_tile(ci + 1, (ci + 1) & 1);
            CP_WAIT(1);
        } else {
            CP_WAIT(0);
        }
        __syncthreads();

        const uint32_t Abase = smem_u32(sm + buf * GK_BUF);
        const uint32_t Bbase = Abase + 16384;

#pragma unroll
        for (int kk8 = 0; kk8 < 8; kk8 += 2) {
            uint32_t a[2][4], b[4][4];
#pragma unroll
            for (int mt = 0; mt < 2; ++mt) {
                const int row = warp_m * 32 + mt * 16 + (lane & 15);
                ldm_x4(a[mt], Abase + sw128(row * 128 + (kk8 + (lane >> 4)) * 16));
            }
#pragma unroll
            for (int ng = 0; ng < 4; ++ng) {
                const int mat  = lane >> 3;
                const int nrow = warp_n * 64 + ng * 16 + ((mat >> 1) << 3) + (lane & 7);
                ldm_x4(b[ng], Bbase + sw128(nrow * 128 + (kk8 + (mat & 1)) * 16));
            }
#pragma unroll
            for (int mt = 0; mt < 2; ++mt)
#pragma unroll
                for (int nt = 0; nt < 8; ++nt)
                    mma_bf16(acc[mt][nt], a[mt], &b[nt >> 1][(nt & 1) * 2]);
        }
        __syncthreads();
    }

    // epilogue: bias + scale, split to bf16 hi/lo, scatter to [B,H,T,dh]
#pragma unroll
    for (int mt = 0; mt < 2; ++mt) {
        const int r0 = bm + warp_m * 32 + mt * 16 + (lane >> 2);
        const int r1 = r0 + 8;
        const int b0_ = r0 >> 11, t0 = r0 & (Tn - 1);
        const int b1_ = r1 >> 11, t1 = r1 & (Tn - 1);
#pragma unroll
        for (int nt = 0; nt < 8; ++nt) {
            const int col = bn + warp_n * 64 + nt * 8 + (lane & 3) * 2;
            const int hh = col >> 6, dd = col & 63;
            const float bb0 = bias[col], bb1 = bias[col + 1];
            float v00 = (acc[mt][nt][0] + bb0) * sc, v01 = (acc[mt][nt][1] + bb1) * sc;
            float v10 = (acc[mt][nt][2] + bb0) * sc, v11 = (acc[mt][nt][3] + bb1) * sc;
            uint32_t h0, l0, h1, l1;
            split2(v00, v01, h0, l0);
            split2(v10, v11, h1, l1);
            const size_t i0 = (((size_t)(b0_ * Hn + hh) * Tn + t0) << 6) + dd;
            const size_t i1 = (((size_t)(b1_ * Hn + hh) * Tn + t1) << 6) + dd;
            *(uint32_t*)&dhi[i0] = h0;  *(uint32_t*)&dlo[i0] = l0;
            *(uint32_t*)&dhi[i1] = h1;  *(uint32_t*)&dlo[i1] = l1;
        }
    }
}

// ---------------------------------------------------------------------------
// Tensor-core flash attention (FA2-style), split-bf16 3-pass for both GEMMs.
// CTA: 128 q-rows, kv tiles of 64. 8 warps x 16 rows. 96KB smem.
// Smem: Qhi[0,16K) Qlo[16K,32K) | 2 x { Khi 8K | Klo 8K | Vhi 8K | Vlo 8K }
// ---------------------------------------------------------------------------
#define AT_SMEM (32768 + 2*32768)     // 96 KB

__global__ __launch_bounds__(256, 1) void attn_mma()
{
    extern __shared__ __align__(1024) char sm[];
    const uint32_t sb = smem_u32(sm);

    const int tid = threadIdx.x, lane = tid & 31, w = tid >> 5;
    const int qt = gridDim.x - 1 - blockIdx.x;     // heavy CTAs first
    const int h  = blockIdx.y, b = blockIdx.z;
    const int qbase = qt * 128;
    const size_t bh_off = ((size_t)(b * Hn + h)) * Tn * DHn;

    const __nv_bfloat16* __restrict__ Qh = g_qhi + bh_off;
    const __nv_bfloat16* __restrict__ Ql = g_qlo + bh_off;
    const __nv_bfloat16* __restrict__ Kh = g_khi + bh_off;
    const __nv_bfloat16* __restrict__ Kl = g_klo + bh_off;
    const __nv_bfloat16* __restrict__ Vh = g_vhi + bh_off;
    const __nv_bfloat16* __restrict__ Vl = g_vlo + bh_off;

    auto issue_kv = [&](int kt2, int buf) {
        const uint32_t kb = sb + 32768 + buf * 32768;
        const int kvb = kt2 * 64;
#pragma unroll
        for (int it = 0; it < 2; ++it) {
            const int v = tid + it * 256;          // 0..511
            const int row = v >> 3, c = v & 7;
            const uint32_t so = sw128(row * 128 + c * 16);
            const size_t go = (size_t)(kvb + row) * DHn + c * 8;
            cp_async16(kb +     0 + so, Kh + go);
            cp_async16(kb +  8192 + so, Kl + go);
            cp_async16(kb + 16384 + so, Vh + go);
            cp_async16(kb + 24576 + so, Vl + go);
        }
        CP_COMMIT();
    };

    // prologue: Q tiles (hi+lo), then kv tile 0
#pragma unroll
    for (int it = 0; it < 4; ++it) {
        const int v = tid + it * 256;              // 0..1023
        const int row = v >> 3, c = v & 7;
        const uint32_t so = sw128(row * 128 + c * 16);
        const size_t go = (size_t)(qbase + row) * DHn + c * 8;
        cp_async16(sb + so,         Qh + go);
        cp_async16(sb + 16384 + so, Ql + go);
    }
    CP_COMMIT();
    issue_kv(0, 0);
    CP_WAIT(1);               // Q group done (kv0 may be pending)
    __syncthreads();

    // hoist Q fragments into registers (loop-invariant)
    uint32_t qah[4][4], qal[4][4];
    {
        const int row = w * 16 + (lane & 15);
#pragma unroll
        for (int kc = 0; kc < 4; ++kc) {
            const uint32_t off = sw128(row * 128 + kc * 32 + (lane >> 4) * 16);
            ldm_x4(qah[kc], sb + off);
            ldm_x4(qal[kc], sb + 16384 + off);
        }
    }

    float o[8][4];
#pragma unroll
    for (int nt = 0; nt < 8; nt++)
#pragma unroll
        for (int j = 0; j < 4; j++) o[nt][j] = 0.f;
    float m2[2] = {-1e30f, -1e30f};
    float l2[2] = {0.f, 0.f};

    const int ntiles = (qbase >> 6) + 2;
    const int rowb = qbase + w * 16;

    for (int kt = 0; kt < ntiles; ++kt) {
        const int buf = kt & 1;
        if (kt + 1 < ntiles) { issue_kv(kt + 1, buf ^ 1); CP_WAIT(1); }
        else                 { CP_WAIT(0); }
        __syncthreads();

        const uint32_t kb = sb + 32768 + buf * 32768;

        // ---- S = Q K^T (3-pass split) ----
        float s[8][4];
#pragma unroll
        for (int nt = 0; nt < 8; nt++)
#pragma unroll
            for (int j = 0; j < 4; j++) s[nt][j] = 0.f;

#pragma unroll
        for (int kc = 0; kc < 4; ++kc) {
            const int mat = lane >> 3;
#pragma unroll
            for (int pg = 0; pg < 4; ++pg) {
                uint32_t bh4[4], bl4[4];
                const int nrow = pg * 16 + ((mat >> 1) << 3) + (lane & 7);
                const uint32_t off = sw128(nrow * 128 + kc * 32 + (mat & 1) * 16);
                ldm_x4(bh4, kb + off);
                ldm_x4(bl4, kb + 8192 + off);
                mma_bf16(s[2*pg],   qah[kc], bh4 + 0);
                mma_bf16(s[2*pg+1], qah[kc], bh4 + 2);
                mma_bf16(s[2*pg],   qah[kc], bl4 + 0);
                mma_bf16(s[2*pg+1], qah[kc], bl4 + 2);
                mma_bf16(s[2*pg],   qal[kc], bh4 + 0);
                mma_bf16(s[2*pg+1], qal[kc], bh4 + 2);
            }
        }

        // ---- causal mask ----
        const int kvb = kt * 64;
        if (kvb + 63 > rowb) {
#pragma unroll
            for (int nt = 0; nt < 8; ++nt) {
                const int c0 = kvb + nt * 8 + (lane & 3) * 2;
                const int r0 = rowb + (lane >> 2);
                if (c0     > r0)     s[nt][0] = -1e30f;
                if (c0 + 1 > r0)     s[nt][1] = -1e30f;
                if (c0     > r0 + 8) s[nt][2] = -1e30f;
                if (c0 + 1 > r0 + 8) s[nt][3] = -1e30f;
            }
        }

        // ---- online softmax (per row-half) ----
#pragma unroll
        for (int hh = 0; hh < 2; ++hh) {
            float mx = -1e30f;
#pragma unroll
            for (int nt = 0; nt < 8; ++nt)
                mx = fmaxf(mx, fmaxf(s[nt][2*hh], s[nt][2*hh+1]));
            mx = fmaxf(mx, __shfl_xor_sync(0xffffffffu, mx, 1));
            mx = fmaxf(mx, __shfl_xor_sync(0xffffffffu, mx, 2));
            const float mnew = fmaxf(m2[hh], mx);
            const float f = __expf(m2[hh] - mnew);
            m2[hh] = mnew;
            float sum = 0.f;
#pragma unroll
            for (int nt = 0; nt < 8; ++nt) {
                const float p0 = __expf(s[nt][2*hh]   - mnew);
                const float p1 = __expf(s[nt][2*hh+1] - mnew);
                s[nt][2*hh] = p0; s[nt][2*hh+1] = p1;
                sum += p0 + p1;
            }
            sum += __shfl_xor_sync(0xffffffffu, sum, 1);
            sum += __shfl_xor_sync(0xffffffffu, sum, 2);
            l2[hh] = l2[hh] * f + sum;
#pragma unroll
            for (int nt = 0; nt < 8; ++nt) {
                o[nt][2*hh]   *= f;
                o[nt][2*hh+1] *= f;
            }
        }

        // ---- O += P V (3-pass split; P frags straight from regs) ----
#pragma unroll
        for (int kc = 0; kc < 4; ++kc) {
            uint32_t ph[4], pl[4];
            split2(s[2*kc][0],   s[2*kc][1],   ph[0], pl[0]);
            split2(s[2*kc][2],   s[2*kc][3],   ph[1], pl[1]);
            split2(s[2*kc+1][0], s[2*kc+1][1], ph[2], pl[2]);
            split2(s[2*kc+1][2], s[2*kc+1][3], ph[3], pl[3]);
            const int mat = lane >> 3;
#pragma unroll
            for (int pg = 0; pg < 4; ++pg) {
                uint32_t vh4[4], vl4[4];
                const int vrow = kc * 16 + ((mat & 1) << 3) + (lane & 7);
                const uint32_t off = sw128(vrow * 128 + (2 * pg + (mat >> 1)) * 16);
                ldm_x4t(vh4, kb + 16384 + off);
                ldm_x4t(vl4, kb + 24576 + off);
                mma_bf16(o[2*pg],   ph, vh4 + 0);
                mma_bf16(o[2*pg+1], ph, vh4 + 2);
                mma_bf16(o[2*pg],   ph, vl4 + 0);
                mma_bf16(o[2*pg+1], ph, vl4 + 2);
                mma_bf16(o[2*pg],   pl, vh4 + 0);
                mma_bf16(o[2*pg+1], pl, vh4 + 2);
            }
        }
        __syncthreads();   // protect buffer before next issue
    }

    // ---- write O / l to merged-head layout ----
#pragma unroll
    for (int hh = 0; hh < 2; ++hh) {
        const float inv = 1.f / l2[hh];
        const int row = rowb + (lane >> 2) + hh * 8;
#pragma unroll
        for (int nt = 0; nt < 8; ++nt) {
            float2 val = make_float2(o[nt][2*hh] * inv, o[nt][2*hh+1] * inv);
            *(float2*)&g_attn[((size_t)(b * Tn + row)) * Dn + h * 64 + nt * 8 + (lane & 3) * 2] = val;
        }
    }
}

// ---------------------------------------------------------------------------
// Residual + LayerNorm
// ---------------------------------------------------------------------------
__global__ __launch_bounds__(256) void resid_ln(
    const float* __restrict__ x,
    const float* __restrict__ gamma,
    const float* __restrict__ beta,
    float* __restrict__ out)
{
    const int row = blockIdx.x;
    const int tid = threadIdx.x;
    const float* xr = x + (size_t)row * Dn;
    const float* ar = g_attn + (size_t)row * Dn;

    float v[4];
    float s = 0.f, sq = 0.f;
#pragma unroll
    for (int j = 0; j < 4; j++) {
        const int c = tid + j * 256;
        const float val = ar[c] + xr[c];
        v[j] = val;
        s += val;
        sq += val * val;
    }
#pragma unroll
    for (int off = 16; off > 0; off >>= 1) {
        s  += __shfl_down_sync(0xffffffffu, s, off);
        sq += __shfl_down_sync(0xffffffffu, sq, off);
    }
    __shared__ float sh[16];
    const int wid = tid >> 5, lane = tid & 31;
    if (lane == 0) { sh[wid] = s; sh[wid + 8] = sq; }
    __syncthreads();
    if (wid == 0) {
        float a  = (lane < 8) ? sh[lane] : 0.f;
        float b2 = (lane < 8) ? sh[lane + 8] : 0.f;
#pragma unroll
        for (int off = 4; off > 0; off >>= 1) {
            a  += __shfl_down_sync(0xffffffffu, a, off);
            b2 += __shfl_down_sync(0xffffffffu, b2, off);
        }
        if (lane == 0) {
            const float mean = a * (1.f / Dn);
            const float var  = b2 * (1.f / Dn) - mean * mean;
            sh[0] = mean;
            sh[1] = rsqrtf(var + 1e-5f);
        }
    }
    __syncthreads();
    const float mean = sh[0], rstd = sh[1];
#pragma unroll
    for (int j = 0; j < 4; j++) {
        const int c = tid + j * 256;
        out[(size_t)row * Dn + c] = (v[j] - mean) * rstd * gamma[c] + beta[c];
    }
}

// ---------------------------------------------------------------------------
extern "C" void kernel_launch(void* const* d_in, const int* in_sizes, int n_in,
                              void* d_out, int out_size)
{
    const float* x     = (const float*)d_in[0];
    const float* Wq    = (const float*)d_in[1];
    const float* bq    = (const float*)d_in[2];
    const float* Wk    = (const float*)d_in[3];
    const float* bk    = (const float*)d_in[4];
    const float* Wv    = (const float*)d_in[5];
    const float* bv    = (const float*)d_in[6];
    const float* gamma = (const float*)d_in[7];
    const float* beta  = (const float*)d_in[8];
    float* out = (float*)d_out;

    static bool attr_set = false;
    if (!attr_set) {
        cudaFuncSetAttribute(qkv_gemm_mma, cudaFuncAttributeMaxDynamicSharedMemorySize, GK_SMEM);
        cudaFuncSetAttribute(attn_mma, cudaFuncAttributeMaxDynamicSharedMemorySize, AT_SMEM);
        attr_set = true;
    }

    // bf16 hi/lo splits of x and W
    __nv_bfloat16 *xhi, *xlo, *whi, *wlo;
    cudaGetSymbolAddress((void**)&xhi, g_xhi);
    cudaGetSymbolAddress((void**)&xlo, g_xlo);
    cudaGetSymbolAddress((void**)&whi, g_Whi);
    cudaGetSymbolAddress((void**)&wlo, g_Wlo);

    split_bf16<<<(NROWS * Dn / 4 + 255) / 256, 256>>>(x, xhi, xlo, NROWS * Dn / 4);
    split_bf16<<<(Dn * Dn / 4 + 255) / 256, 256>>>(Wq, whi + 0 * (size_t)Dn * Dn, wlo + 0 * (size_t)Dn * Dn, Dn * Dn / 4);
    split_bf16<<<(Dn * Dn / 4 + 255) / 256, 256>>>(Wk, whi + 1 * (size_t)Dn * Dn, wlo + 1 * (size_t)Dn * Dn, Dn * Dn / 4);
    split_bf16<<<(Dn * Dn / 4 + 255) / 256, 256>>>(Wv, whi + 2 * (size_t)Dn * Dn, wlo + 2 * (size_t)Dn * Dn, Dn * Dn / 4);

    // tensor-core QKV projections -> bf16 hi/lo Q/K/V
    qkv_gemm_mma<<<dim3(Dn / 128, NROWS / 128, 3), 256, GK_SMEM>>>(bq, bk, bv);

    // tensor-core flash attention
    attn_mma<<<dim3(Tn / 128, Hn, Bn), 256, AT_SMEM>>>();

    // Residual + LayerNorm
    resid_ln<<<NROWS, 256>>>(x, gamma, beta, out);
}